// round 15
// baseline (speedup 1.0000x reference)
#include <cuda_runtime.h>
#include <cuda_bf16.h>
#include <cstdint>

// Focal cross-entropy sum over N rows, 2 classes — single fused kernel.
// Base-2 domain:  e = d*log2e ; ex = 2^e ; u = 1+ex ; L = lg2(u)
//   q0 = 1/u ; q1 = ex/u
//   per-row reduced loss:  A + t*(B/3 - A/4),  A = L*q1^2, B = (L-e)*q0^2
//   total = 0.75*ln2 * sum  (scale applied ONCE at the final write)
//
// R15: break the warp/load coupling with a bulk-async SMEM pipeline.
// All warp-side levers are exhausted (geometry/MLP/instr-count/cache-policy
// all neutral-or-worse; DRAM pinned ~69%). cp.async.bulk + mbarrier keeps
// ~3 x 12KB tiles in flight per CTA via the copy engine, independent of warp
// scheduling. Compute = R12 packed f32x2 math, from SMEM.

static constexpr int BLOCKS  = 1024;
static constexpr int THREADS = 512;
static constexpr int STAGES  = 3;
static constexpr int TILE_PAIRS = THREADS;               // 512 pairs per tile
static constexpr int PRED_STAGE_BYTES = TILE_PAIRS * 16; // 8192
static constexpr int GOLD_STAGE_BYTES = TILE_PAIRS * 8;  // 4096
static constexpr int STAGE_BYTES = PRED_STAGE_BYTES + GOLD_STAGE_BYTES; // 12288

__device__ float g_partials[BLOCKS];
__device__ unsigned int g_ticket = 0;   // returns to 0 every run -> graph-replay safe

// ---- packed f32x2 helpers (sm_100a) ----
typedef unsigned long long u64;
__device__ __forceinline__ u64 pk2(float lo, float hi) {
    u64 r; asm("mov.b64 %0, {%1, %2};" : "=l"(r) : "f"(lo), "f"(hi)); return r;
}
__device__ __forceinline__ void upk2(float& lo, float& hi, u64 v) {
    asm("mov.b64 {%0, %1}, %2;" : "=f"(lo), "=f"(hi) : "l"(v));
}
__device__ __forceinline__ u64 add2(u64 a, u64 b) {
    u64 r; asm("add.rn.f32x2 %0, %1, %2;" : "=l"(r) : "l"(a), "l"(b)); return r;
}
__device__ __forceinline__ u64 mul2(u64 a, u64 b) {
    u64 r; asm("mul.rn.f32x2 %0, %1, %2;" : "=l"(r) : "l"(a), "l"(b)); return r;
}
__device__ __forceinline__ u64 fma2(u64 a, u64 b, u64 c) {
    u64 r; asm("fma.rn.f32x2 %0, %1, %2, %3;" : "=l"(r) : "l"(a), "l"(b), "l"(c)); return r;
}
__device__ __forceinline__ float ex2f(float x){ float r; asm("ex2.approx.f32 %0, %1;" : "=f"(r) : "f"(x)); return r; }
__device__ __forceinline__ float lg2f(float x){ float r; asm("lg2.approx.f32 %0, %1;" : "=f"(r) : "f"(x)); return r; }
__device__ __forceinline__ float rcpf(float x){ float r; asm("rcp.approx.f32 %0, %1;" : "=f"(r) : "f"(x)); return r; }

static constexpr float L2E   = 1.4426950408889634f;          // log2(e)
static constexpr float SCALE = 0.75f * 0.6931471805599453f;  // 0.75*ln2

// Scalar reduced-domain row loss (fallback/tail path)
__device__ __forceinline__ float row_core(float p0, float p1, float gold) {
    float d  = p1 - p0;
    float e  = d * L2E;
    float ex = ex2f(e);
    float u  = 1.0f + ex;
    float L  = lg2f(u);
    float q0 = rcpf(u);
    float q1 = ex * q0;
    float A  = L * (q1 * q1);
    float B  = (L - e) * (q0 * q0);
    float C  = B * 0.33333334f - A * 0.25f;
    float t  = (gold >= 0.5f) ? 1.0f : 0.0f;
    return A + t * C;
}

// Packed 2-row body: rows (p.x,p.y) and (p.z,p.w), golds (g.x,g.y).
__device__ __forceinline__ void rows2_packed(float4 p, float2 g, u64& acc2,
                                             u64 KM1, u64 K13, u64 KM025) {
    float da = p.y - p.x,   db = p.w - p.z;
    float ea = da * L2E,    eb = db * L2E;
    float xa = ex2f(ea),    xb = ex2f(eb);
    float ua = 1.0f + xa,   ub = 1.0f + xb;
    float La = lg2f(ua),    Lb = lg2f(ub);
    float ra = rcpf(ua),    rb = rcpf(ub);

    u64 q0 = pk2(ra, rb);
    u64 ex = pk2(xa, xb);
    u64 L  = pk2(La, Lb);
    u64 e2 = pk2(ea, eb);

    u64 q1  = mul2(ex, q0);
    u64 q1s = mul2(q1, q1);
    u64 A   = mul2(L, q1s);
    u64 Le  = fma2(e2, KM1, L);               // L - e
    u64 q0s = mul2(q0, q0);
    u64 B   = mul2(Le, q0s);
    u64 C   = fma2(B, K13, mul2(A, KM025));   // B/3 - A/4

    float ta = (g.x >= 0.5f) ? 1.0f : 0.0f;
    float tb = (g.y >= 0.5f) ? 1.0f : 0.0f;
    u64 t2 = pk2(ta, tb);

    acc2 = add2(acc2, A);
    acc2 = fma2(C, t2, acc2);
}

// ---- mbarrier / bulk-copy helpers ----
__device__ __forceinline__ uint32_t smem_u32(const void* p) {
    uint32_t a;
    asm("{ .reg .u64 t; cvta.to.shared.u64 t, %1; cvt.u32.u64 %0, t; }" : "=r"(a) : "l"(p));
    return a;
}
__device__ __forceinline__ void mbar_init(uint32_t mbar, uint32_t count) {
    asm volatile("mbarrier.init.shared.b64 [%0], %1;" :: "r"(mbar), "r"(count) : "memory");
}
__device__ __forceinline__ void mbar_expect_tx(uint32_t mbar, uint32_t bytes) {
    asm volatile("mbarrier.arrive.expect_tx.shared.b64 _, [%0], %1;" :: "r"(mbar), "r"(bytes) : "memory");
}
__device__ __forceinline__ void mbar_wait(uint32_t mbar, uint32_t parity) {
    asm volatile(
        "{\n\t"
        ".reg .pred P;\n\t"
        "WL_%=:\n\t"
        "mbarrier.try_wait.parity.acquire.cta.shared::cta.b64 P, [%0], %1, 0x989680;\n\t"
        "@P bra WD_%=;\n\t"
        "bra WL_%=;\n\t"
        "WD_%=:\n\t"
        "}"
        :: "r"(mbar), "r"(parity) : "memory");
}
__device__ __forceinline__ void bulk_g2s(uint32_t dst_smem, const void* src, uint32_t bytes, uint32_t mbar) {
    asm volatile(
        "cp.async.bulk.shared::cta.global.mbarrier::complete_tx::bytes [%0], [%1], %2, [%3];"
        :: "r"(dst_smem), "l"(src), "r"(bytes), "r"(mbar) : "memory");
}

__global__ void __launch_bounds__(THREADS)
focal_sum_fused(const float* __restrict__ pred,
                const float* __restrict__ gold,
                float* __restrict__ out,
                int n_rows) {
    __shared__ __align__(128) unsigned char sm_pred[STAGES][PRED_STAGE_BYTES];
    __shared__ __align__(128) unsigned char sm_gold[STAGES][GOLD_STAGE_BYTES];
    __shared__ __align__(8)  unsigned long long sm_mbar[STAGES];
    __shared__ float warp_sums[THREADS / 32];
    __shared__ bool  is_last;

    const int tid = threadIdx.x;

    // packed constants
    const u64 KM1   = pk2(-1.0f, -1.0f);
    const u64 K13   = pk2(0.33333334f, 0.33333334f);
    const u64 KM025 = pk2(-0.25f, -0.25f);

    u64   acc2  = pk2(0.0f, 0.0f);
    float acc_s = 0.0f;

    int n_pairs = n_rows >> 1;
    bool fast = ((n_rows & 1) == 0) && (n_pairs % (BLOCKS * TILE_PAIRS) == 0);

    if (fast) {
        // ---- bulk-async pipeline path (benchmark shape) ----
        int tiles_per_block = n_pairs / (BLOCKS * TILE_PAIRS);   // 16 for N=16.7M

        uint32_t mb[STAGES];
        #pragma unroll
        for (int s = 0; s < STAGES; s++) mb[s] = smem_u32(&sm_mbar[s]);

        if (tid == 0) {
            #pragma unroll
            for (int s = 0; s < STAGES; s++) mbar_init(mb[s], 1);
        }
        __syncthreads();

        const char* predc = reinterpret_cast<const char*>(pred);
        const char* goldc = reinterpret_cast<const char*>(gold);

        // Prologue: fill the ring
        if (tid == 0) {
            #pragma unroll
            for (int k = 0; k < STAGES; k++) {
                if (k < tiles_per_block) {
                    long long gt = (long long)blockIdx.x + (long long)k * BLOCKS;
                    long long gp = gt * TILE_PAIRS;
                    mbar_expect_tx(mb[k], STAGE_BYTES);
                    bulk_g2s(smem_u32(sm_pred[k]), predc + gp * 16, PRED_STAGE_BYTES, mb[k]);
                    bulk_g2s(smem_u32(sm_gold[k]), goldc + gp * 8,  GOLD_STAGE_BYTES, mb[k]);
                }
            }
        }

        for (int t = 0; t < tiles_per_block; t++) {
            int s = t % STAGES;
            uint32_t parity = (uint32_t)((t / STAGES) & 1);
            mbar_wait(mb[s], parity);

            float4 p = reinterpret_cast<const float4*>(sm_pred[s])[tid];
            float2 g = reinterpret_cast<const float2*>(sm_gold[s])[tid];
            rows2_packed(p, g, acc2, KM1, K13, KM025);

            __syncthreads();   // all consumers done with stage s

            int tn = t + STAGES;
            if (tn < tiles_per_block && tid == 0) {
                long long gt = (long long)blockIdx.x + (long long)tn * BLOCKS;
                long long gp = gt * TILE_PAIRS;
                mbar_expect_tx(mb[s], STAGE_BYTES);
                bulk_g2s(smem_u32(sm_pred[s]), predc + gp * 16, PRED_STAGE_BYTES, mb[s]);
                bulk_g2s(smem_u32(sm_gold[s]), goldc + gp * 8,  GOLD_STAGE_BYTES, mb[s]);
            }
        }
    } else {
        // ---- generic fallback (any shape): R12 global-load loop ----
        const float4* pred4 = reinterpret_cast<const float4*>(pred);
        const float2* gold2 = reinterpret_cast<const float2*>(gold);
        const int TILE   = THREADS * 2;
        const int STRIDE = BLOCKS * TILE;
        for (int base = blockIdx.x * TILE + tid; base < n_pairs; base += STRIDE) {
            int i1 = base + THREADS;
            float4 pA = pred4[base];
            float2 gA = gold2[base];
            if (i1 < n_pairs) {
                float4 pB = pred4[i1];
                float2 gB = gold2[i1];
                rows2_packed(pA, gA, acc2, KM1, K13, KM025);
                rows2_packed(pB, gB, acc2, KM1, K13, KM025);
            } else {
                rows2_packed(pA, gA, acc2, KM1, K13, KM025);
            }
        }
        if ((n_rows & 1) && blockIdx.x == 0 && tid == 0) {
            int r = n_rows - 1;
            acc_s += row_core(pred[2 * r], pred[2 * r + 1], gold[r]);
        }
    }

    float lo, hi;
    upk2(lo, hi, acc2);
    float acc = lo + hi + acc_s;

    // Block reduction
    #pragma unroll
    for (int off = 16; off > 0; off >>= 1)
        acc += __shfl_xor_sync(0xFFFFFFFFu, acc, off);

    int lane = tid & 31;
    int wid  = tid >> 5;
    if (lane == 0) warp_sums[wid] = acc;
    __syncthreads();

    if (wid == 0) {
        float v = (lane < THREADS / 32) ? warp_sums[lane] : 0.0f;
        #pragma unroll
        for (int off = 16; off > 0; off >>= 1)
            v += __shfl_xor_sync(0xFFFFFFFFu, v, off);
        if (lane == 0) {
            g_partials[blockIdx.x] = v;
            __threadfence();
            unsigned int tk = atomicAdd(&g_ticket, 1u);
            is_last = (tk == BLOCKS - 1);
        }
    }
    __syncthreads();

    // Last-arriving block: deterministic final reduction (fixed order).
    if (is_last) {
        float v = 0.0f;
        for (int i = tid; i < BLOCKS; i += THREADS)
            v += g_partials[i];

        #pragma unroll
        for (int off = 16; off > 0; off >>= 1)
            v += __shfl_xor_sync(0xFFFFFFFFu, v, off);
        if (lane == 0) warp_sums[wid] = v;
        __syncthreads();
        if (wid == 0) {
            float w = (lane < THREADS / 32) ? warp_sums[lane] : 0.0f;
            #pragma unroll
            for (int off = 16; off > 0; off >>= 1)
                w += __shfl_xor_sync(0xFFFFFFFFu, w, off);
            if (lane == 0) {
                out[0] = w * SCALE;  // 0.75*ln2, factored out of the whole sum
                g_ticket = 0;        // reset for next graph replay
            }
        }
    }
}

extern "C" void kernel_launch(void* const* d_in, const int* in_sizes, int n_in,
                              void* d_out, int out_size) {
    const float* pred = (const float*)d_in[0];   // [N, 2] f32
    const float* gold = (const float*)d_in[1];   // [N]    f32
    int n_rows = in_sizes[1];

    focal_sum_fused<<<BLOCKS, THREADS>>>(pred, gold, (float*)d_out, n_rows);
}

// round 16
// speedup vs baseline: 1.1034x; 1.1034x over previous
#include <cuda_runtime.h>
#include <cuda_bf16.h>

// Focal cross-entropy sum over N rows, 2 classes — single fused kernel.
// Base-2 domain:  e = d*log2e ; ex = 2^e ; u = 1+ex ; L = lg2(u)
//   q0 = 1/u ; q1 = ex/u
//   per-row reduced loss:  A + t*(B/3 - A/4),  A = L*q1^2, B = (L-e)*q0^2
//   total = 0.75*ln2 * sum  (scale applied ONCE at the final write)
//   t = gold>=0.5
//
// R16 = R12 verbatim (committed final form). Ladder conclusion: six
// independent mechanisms (strided/coalesced loads, high/low MLP, instr-count
// cut, L1 bypass, bulk-async DMA) all plateau at 5.5-5.6 TB/s — the achieved
// streaming ceiling for this read-only mix on this part. R12 is the best
// measured config: ncu 36.48us, DRAM 68.9%, issue 38.9%, rel_err 7.9e-8.

static constexpr int BLOCKS  = 1024;
static constexpr int THREADS = 512;

__device__ float g_partials[BLOCKS];
__device__ unsigned int g_ticket = 0;   // returns to 0 every run -> graph-replay safe

// ---- packed f32x2 helpers (sm_100a) ----
typedef unsigned long long u64;
__device__ __forceinline__ u64 pk2(float lo, float hi) {
    u64 r; asm("mov.b64 %0, {%1, %2};" : "=l"(r) : "f"(lo), "f"(hi)); return r;
}
__device__ __forceinline__ void upk2(float& lo, float& hi, u64 v) {
    asm("mov.b64 {%0, %1}, %2;" : "=f"(lo), "=f"(hi) : "l"(v));
}
__device__ __forceinline__ u64 add2(u64 a, u64 b) {
    u64 r; asm("add.rn.f32x2 %0, %1, %2;" : "=l"(r) : "l"(a), "l"(b)); return r;
}
__device__ __forceinline__ u64 mul2(u64 a, u64 b) {
    u64 r; asm("mul.rn.f32x2 %0, %1, %2;" : "=l"(r) : "l"(a), "l"(b)); return r;
}
__device__ __forceinline__ u64 fma2(u64 a, u64 b, u64 c) {
    u64 r; asm("fma.rn.f32x2 %0, %1, %2, %3;" : "=l"(r) : "l"(a), "l"(b), "l"(c)); return r;
}
__device__ __forceinline__ float ex2f(float x){ float r; asm("ex2.approx.f32 %0, %1;" : "=f"(r) : "f"(x)); return r; }
__device__ __forceinline__ float lg2f(float x){ float r; asm("lg2.approx.f32 %0, %1;" : "=f"(r) : "f"(x)); return r; }
__device__ __forceinline__ float rcpf(float x){ float r; asm("rcp.approx.f32 %0, %1;" : "=f"(r) : "f"(x)); return r; }

static constexpr float L2E   = 1.4426950408889634f;  // log2(e)
static constexpr float SCALE = 0.75f * 0.6931471805599453f;  // 0.75*ln2

// Scalar reduced-domain row loss (tail path): A + t*(B/3 - A/4)
__device__ __forceinline__ float row_core(float p0, float p1, float gold) {
    float d  = p1 - p0;
    float e  = d * L2E;
    float ex = ex2f(e);
    float u  = 1.0f + ex;
    float L  = lg2f(u);
    float q0 = rcpf(u);
    float q1 = ex * q0;
    float A  = L * (q1 * q1);
    float B  = (L - e) * (q0 * q0);
    float C  = B * 0.33333334f - A * 0.25f;
    float t  = (gold >= 0.5f) ? 1.0f : 0.0f;
    return A + t * C;
}

// Packed 2-row body: rows (p.x,p.y) and (p.z,p.w), golds (g.x,g.y).
__device__ __forceinline__ void rows2_packed(float4 p, float2 g, u64& acc2,
                                             u64 KM1, u64 K13, u64 KM025) {
    float da = p.y - p.x,   db = p.w - p.z;
    float ea = da * L2E,    eb = db * L2E;
    float xa = ex2f(ea),    xb = ex2f(eb);
    float ua = 1.0f + xa,   ub = 1.0f + xb;
    float La = lg2f(ua),    Lb = lg2f(ub);
    float ra = rcpf(ua),    rb = rcpf(ub);

    u64 q0 = pk2(ra, rb);
    u64 ex = pk2(xa, xb);
    u64 L  = pk2(La, Lb);
    u64 e2 = pk2(ea, eb);

    u64 q1  = mul2(ex, q0);
    u64 q1s = mul2(q1, q1);
    u64 A   = mul2(L, q1s);
    u64 Le  = fma2(e2, KM1, L);          // L - e
    u64 q0s = mul2(q0, q0);
    u64 B   = mul2(Le, q0s);
    u64 C   = fma2(B, K13, mul2(A, KM025));   // B/3 - A/4

    float ta = (g.x >= 0.5f) ? 1.0f : 0.0f;
    float tb = (g.y >= 0.5f) ? 1.0f : 0.0f;
    u64 t2 = pk2(ta, tb);

    acc2 = add2(acc2, A);
    acc2 = fma2(C, t2, acc2);
}

__global__ void __launch_bounds__(THREADS)
focal_sum_fused(const float* __restrict__ pred,
                const float* __restrict__ gold,
                float* __restrict__ out,
                int n_rows) {
    const float4* pred4 = reinterpret_cast<const float4*>(pred);  // 1 float4 = 2 rows
    const float2* gold2 = reinterpret_cast<const float2*>(gold);  // 1 float2 = 2 rows

    int n_pairs = n_rows >> 1;            // row-pair units
    const int TILE   = THREADS * 2;       // pairs per block per iter
    const int STRIDE = BLOCKS * TILE;

    // packed constants (loop-invariant, hoisted by ptxas)
    const u64 KM1   = pk2(-1.0f, -1.0f);
    const u64 K13   = pk2(0.33333334f, 0.33333334f);
    const u64 KM025 = pk2(-0.25f, -0.25f);

    u64 acc2 = pk2(0.0f, 0.0f);
    float acc_s = 0.0f;   // tail-path scalar accumulator

    for (int base = blockIdx.x * TILE + threadIdx.x; base < n_pairs; base += STRIDE) {
        int i1 = base + THREADS;
        float4 pA = pred4[base];
        float2 gA = gold2[base];
        if (i1 < n_pairs) {
            float4 pB = pred4[i1];
            float2 gB = gold2[i1];
            rows2_packed(pA, gA, acc2, KM1, K13, KM025);
            rows2_packed(pB, gB, acc2, KM1, K13, KM025);
        } else {
            rows2_packed(pA, gA, acc2, KM1, K13, KM025);
        }
    }
    // Tail row (n_rows odd)
    if ((n_rows & 1) && blockIdx.x == 0 && threadIdx.x == 0) {
        int r = n_rows - 1;
        acc_s += row_core(pred[2 * r], pred[2 * r + 1], gold[r]);
    }

    float lo, hi;
    upk2(lo, hi, acc2);
    float acc = lo + hi + acc_s;

    // Block reduction
    #pragma unroll
    for (int off = 16; off > 0; off >>= 1)
        acc += __shfl_xor_sync(0xFFFFFFFFu, acc, off);

    __shared__ float warp_sums[THREADS / 32];
    __shared__ bool  is_last;
    int lane = threadIdx.x & 31;
    int wid  = threadIdx.x >> 5;
    if (lane == 0) warp_sums[wid] = acc;
    __syncthreads();

    if (wid == 0) {
        float v = (lane < THREADS / 32) ? warp_sums[lane] : 0.0f;
        #pragma unroll
        for (int off = 16; off > 0; off >>= 1)
            v += __shfl_xor_sync(0xFFFFFFFFu, v, off);
        if (lane == 0) {
            g_partials[blockIdx.x] = v;
            __threadfence();                         // make partial visible
            unsigned int t = atomicAdd(&g_ticket, 1u);
            is_last = (t == BLOCKS - 1);
        }
    }
    __syncthreads();

    // Last-arriving block performs the deterministic final reduction
    // (fixed summation order regardless of which block arrives last).
    if (is_last) {
        float v = 0.0f;
        for (int i = threadIdx.x; i < BLOCKS; i += THREADS)
            v += g_partials[i];

        #pragma unroll
        for (int off = 16; off > 0; off >>= 1)
            v += __shfl_xor_sync(0xFFFFFFFFu, v, off);
        if (lane == 0) warp_sums[wid] = v;
        __syncthreads();
        if (wid == 0) {
            float w = (lane < THREADS / 32) ? warp_sums[lane] : 0.0f;
            #pragma unroll
            for (int off = 16; off > 0; off >>= 1)
                w += __shfl_xor_sync(0xFFFFFFFFu, w, off);
            if (lane == 0) {
                out[0] = w * SCALE;  // 0.75*ln2, factored out of the whole sum
                g_ticket = 0;        // reset for next graph replay
            }
        }
    }
}

extern "C" void kernel_launch(void* const* d_in, const int* in_sizes, int n_in,
                              void* d_out, int out_size) {
    const float* pred = (const float*)d_in[0];   // [N, 2] f32
    const float* gold = (const float*)d_in[1];   // [N]    f32
    int n_rows = in_sizes[1];

    focal_sum_fused<<<BLOCKS, THREADS>>>(pred, gold, (float*)d_out, n_rows);
}